// round 5
// baseline (speedup 1.0000x reference)
#include <cuda_runtime.h>

// Fixed problem shapes
#define DIMD 272
#define NC   19
#define ZS   20
#define NPAIR 10
#define NROWS 65536
#define NISEG 4096
#define THREADS 128
#define PB_ROWS 128                      // rows per proj block (1 per thread)
#define PROJ_BLOCKS (NROWS / PB_ROWS)    // 512
#define DCHUNK 17                        // d's per stage (272 = 16*17)
#define NSTAGE 16
#define DEPTH 3                          // cp.async ring depth
#define STAGE_WORDS (PB_ROWS * DCHUNK)   // 2176 floats per stage
#define PPT 16                           // points per thread, bounds part
#define GROUPS2 12                       // 12 groups x 10 pair-lanes = 120
#define SEG_CHUNK 2048

typedef unsigned long long ull;

__device__ float g_Z[(size_t)NROWS * ZS];
__device__ int   g_off[NISEG + 1];

__device__ __forceinline__ ull pack2(float lo, float hi) {
    ull r; asm("mov.b64 %0, {%1, %2};" : "=l"(r) : "f"(lo), "f"(hi)); return r;
}
__device__ __forceinline__ void unpack2(ull v, float& lo, float& hi) {
    asm("mov.b64 {%0, %1}, %2;" : "=f"(lo), "=f"(hi) : "l"(v));
}
__device__ __forceinline__ void fma2(ull& d, ull a, ull b) {
    asm("fma.rn.f32x2 %0, %1, %2, %0;" : "+l"(d) : "l"(a), "l"(b));
}
__device__ __forceinline__ void add2(ull& d, ull a) {
    asm("add.rn.f32x2 %0, %0, %1;" : "+l"(d) : "l"(a));
}
__device__ __forceinline__ void cpasync4(unsigned smem, const void* g) {
    asm volatile("cp.async.ca.shared.global [%0], [%1], 4;"
                 :: "r"(smem), "l"(g));
}
__device__ __forceinline__ void cpcommit() {
    asm volatile("cp.async.commit_group;");
}
__device__ __forceinline__ void cpwait1() {
    asm volatile("cp.async.wait_group 1;");
}

// ---------------------------------------------------------------------------
// Fat kernel: blocks [0, PROJ_BLOCKS) compute Z = X@W with a 3-stage cp.async
// pipeline; remaining blocks compute segment boundary offsets.
// ---------------------------------------------------------------------------
__global__ __launch_bounds__(THREADS)
void fat_kernel(const float* __restrict__ X, const float* __restrict__ W,
                const int* __restrict__ segs, int P) {
    if (blockIdx.x < PROJ_BLOCKS) {
        __shared__ __align__(16) float ws[DIMD * ZS];        // 21760 B
        __shared__ float xs[DEPTH][STAGE_WORDS];             // 26112 B

        const int t = threadIdx.x;
        const int row0 = blockIdx.x * PB_ROWS;

        // Issue cp.async for one stage s (rows coalesced: consecutive i ->
        // consecutive global words within a row chunk).
        auto issue_stage = [&](int s) {
            const float* gbase = X + (size_t)row0 * DIMD + s * DCHUNK;
            unsigned sb = (unsigned)__cvta_generic_to_shared(xs[s % DEPTH]);
#pragma unroll
            for (int k = 0; k < DCHUNK; k++) {
                int i  = t + k * THREADS;           // 0..2175
                int r  = i / DCHUNK;
                int dd = i - r * DCHUNK;
                cpasync4(sb + 4u * (unsigned)i, gbase + (size_t)r * DIMD + dd);
            }
        };

        issue_stage(0); cpcommit();
        issue_stage(1); cpcommit();

        // Stage W (padded to 20 cols) while cp.asyncs fly
        for (int i = t; i < DIMD * ZS; i += THREADS) {
            int dd = i / ZS, c = i - dd * ZS;
            ws[i] = (c < NC) ? W[dd * NC + c] : 0.f;
        }

        ull acc[NPAIR];
        const ull z2 = pack2(0.f, 0.f);
#pragma unroll
        for (int j = 0; j < NPAIR; j++) acc[j] = z2;

        for (int s = 0; s < NSTAGE; s++) {
            cpwait1();            // stage s resident
            __syncthreads();      // all writes visible; prior compute done
            if (s + 2 < NSTAGE) issue_stage(s + 2);
            cpcommit();           // empty group ok near the end

            const float* xrow = &xs[s % DEPTH][t * DCHUNK];
            const ulonglong2* wq =
                (const ulonglong2*)(ws + s * DCHUNK * ZS);
#pragma unroll
            for (int dd = 0; dd < DCHUNK; dd++) {
                float xa = xrow[dd];              // stride-17: conflict-free
                ull xaa = pack2(xa, xa);
#pragma unroll
                for (int jj = 0; jj < 5; jj++) {
                    ulonglong2 w = wq[dd * 5 + jj];   // LDS.128 broadcast
                    fma2(acc[2 * jj],     xaa, w.x);
                    fma2(acc[2 * jj + 1], xaa, w.y);
                }
            }
        }

        ulonglong2* za = (ulonglong2*)&g_Z[(size_t)(row0 + t) * ZS];
#pragma unroll
        for (int jj = 0; jj < 5; jj++) {
            ulonglong2 sa; sa.x = acc[2 * jj]; sa.y = acc[2 * jj + 1];
            za[jj] = sa;
        }
    } else {
        // ----------------- segment bounds part -----------------
        const int base = (blockIdx.x - PROJ_BLOCKS) * (THREADS * PPT)
                       + threadIdx.x * PPT;
        if (base >= P) return;
        int vv[PPT];
        const int4* s4 = (const int4*)(segs + base);
#pragma unroll
        for (int q = 0; q < PPT / 4; q++) {
            int4 v = __ldg(s4 + q);
            vv[q*4+0] = v.x; vv[q*4+1] = v.y; vv[q*4+2] = v.z; vv[q*4+3] = v.w;
        }
        int prev = (base == 0) ? -1 : __ldg(segs + base - 1);
#pragma unroll
        for (int k = 0; k < PPT; k++) {
            int s = vv[k];
            if (s != prev)
                for (int q = prev + 1; q <= s; q++) g_off[q] = base + k;
            prev = s;
        }
        if (base + PPT >= P)
            for (int q = prev + 1; q <= NISEG; q++) g_off[q] = P;
    }
}

// ---------------------------------------------------------------------------
// Seg kernel: one block per segment; 12 groups x 10 pair-lanes accumulate
// f32x2 column pairs of Z; mean + bias + sigmoid.
// ---------------------------------------------------------------------------
__global__ __launch_bounds__(128)
void seg_kernel(const int* __restrict__ pidx, const float* __restrict__ bias,
                float* __restrict__ out) {
    const int s = blockIdx.x;
    const int t = threadIdx.x;
    const int start = g_off[s];
    const int end   = g_off[s + 1];

    __shared__ int sp[SEG_CHUNK];
    __shared__ ull sAcc[GROUPS2 * NPAIR];

    const int g = t / NPAIR;        // 0..12 (12 = idle lanes 120..127)
    const int j = t - g * NPAIR;    // column pair
    ull acc = 0;

    for (int base = start; base < end; base += SEG_CHUNK) {
        const int n = min(end - base, SEG_CHUNK);
        for (int i = t; i < n; i += 128) sp[i] = pidx[base + i];
        __syncthreads();
        if (g < GROUPS2) {
#pragma unroll 4
            for (int p = g; p < n; p += GROUPS2) {
                int r = sp[p];
                ull v = *(const ull*)&g_Z[(size_t)r * ZS + 2 * j];
                add2(acc, v);
            }
        }
        __syncthreads();
    }

    if (g < GROUPS2) sAcc[t] = acc;
    __syncthreads();

    if (t < NPAIR) {
        ull total = sAcc[t];
#pragma unroll
        for (int q = 1; q < GROUPS2; q++) add2(total, sAcc[q * NPAIR + t]);
        float f0, f1; unpack2(total, f0, f1);
        float cnt = (float)(end - start);
        float inv = 1.0f / fmaxf(cnt, 1.0f);
        int c0 = 2 * t;
        float x0 = f0 * inv + bias[c0];
        out[(size_t)s * NC + c0] = 1.0f / (1.0f + __expf(-x0));
        if (c0 + 1 < NC) {
            float x1 = f1 * inv + bias[c0 + 1];
            out[(size_t)s * NC + c0 + 1] = 1.0f / (1.0f + __expf(-x1));
        }
    }
}

// ---------------------------------------------------------------------------
extern "C" void kernel_launch(void* const* d_in, const int* in_sizes, int n_in,
                              void* d_out, int out_size) {
    const float* X    = (const float*)d_in[0];
    const float* W    = (const float*)d_in[1];
    const float* b    = (const float*)d_in[2];
    const int*   pidx = (const int*)d_in[3];
    const int*   segs = (const int*)d_in[4];
    float*       out  = (float*)d_out;

    const int P = in_sizes[3];
    const int boundsBlocks = (P + THREADS * PPT - 1) / (THREADS * PPT);

    fat_kernel<<<PROJ_BLOCKS + boundsBlocks, THREADS>>>(X, W, segs, P);
    seg_kernel<<<NISEG, 128>>>(pidx, b, out);
}

// round 6
// speedup vs baseline: 1.1013x; 1.1013x over previous
#include <cuda_runtime.h>

// Fixed problem shapes
#define DIMD 272
#define NC   19
#define ZS   20
#define NPAIR 10
#define NROWS 65536
#define NISEG 4096
#define THREADS 128
#define PB_ROWS 128                      // rows per proj block (1/thread)
#define PROJ_BLOCKS (NROWS / PB_ROWS)    // 512
#define DCHUNK 8                         // d's per stage (272 = 34*8)
#define NSTAGE 34
#define DEPTH 4                          // cp.async ring depth
#define XSTRIDE 12                       // floats per row in stage (48B pad)
#define PPT 16                           // points/thread in bounds part
#define SEGS_PER_BLOCK 8                 // seg kernel: 8 warps = 8 segments

typedef unsigned long long ull;

__device__ float g_Z[(size_t)NROWS * ZS];
__device__ int   g_off[NISEG + 1];

__device__ __forceinline__ ull pack2(float lo, float hi) {
    ull r; asm("mov.b64 %0, {%1, %2};" : "=l"(r) : "f"(lo), "f"(hi)); return r;
}
__device__ __forceinline__ void unpack2(ull v, float& lo, float& hi) {
    asm("mov.b64 {%0, %1}, %2;" : "=f"(lo), "=f"(hi) : "l"(v));
}
__device__ __forceinline__ void fma2(ull& d, ull a, ull b) {
    asm("fma.rn.f32x2 %0, %1, %2, %0;" : "+l"(d) : "l"(a), "l"(b));
}
__device__ __forceinline__ void add2(ull& d, ull a) {
    asm("add.rn.f32x2 %0, %0, %1;" : "+l"(d) : "l"(a));
}
__device__ __forceinline__ void cpasync16(unsigned smem, const void* g) {
    asm volatile("cp.async.cg.shared.global [%0], [%1], 16;"
                 :: "r"(smem), "l"(g));
}
__device__ __forceinline__ void cpcommit() {
    asm volatile("cp.async.commit_group;");
}
__device__ __forceinline__ void cpwait2() {
    asm volatile("cp.async.wait_group 2;");
}

// ---------------------------------------------------------------------------
// Fat kernel: blocks [0, PROJ_BLOCKS) compute Z = X@W (cp.async.16 pipeline);
// remaining blocks compute segment boundary offsets.
// ---------------------------------------------------------------------------
__global__ __launch_bounds__(THREADS)
void fat_kernel(const float* __restrict__ X, const float* __restrict__ W,
                const int* __restrict__ segs, int P) {
    if (blockIdx.x < PROJ_BLOCKS) {
        __shared__ __align__(16) float ws[DIMD * ZS];              // 21760 B
        __shared__ __align__(16) float xs[DEPTH][PB_ROWS * XSTRIDE]; // 24576 B

        const int t = threadIdx.x;
        const int row0 = blockIdx.x * PB_ROWS;

        // Issue one stage: 128 rows x 32 bytes, 2 x cp.async.16 per thread.
        auto issue_stage = [&](int s) {
            const char* gbase = (const char*)(X + (size_t)row0 * DIMD) + s * 32;
            unsigned sb = (unsigned)__cvta_generic_to_shared(xs[s % DEPTH]);
#pragma unroll
            for (int k = 0; k < 2; k++) {
                int i  = t + k * THREADS;        // 0..255
                int r  = i >> 1;
                int f4 = i & 1;
                cpasync16(sb + (unsigned)(r * 48 + f4 * 16),
                          gbase + (size_t)r * (DIMD * 4) + f4 * 16);
            }
        };

        issue_stage(0); cpcommit();
        issue_stage(1); cpcommit();
        issue_stage(2); cpcommit();

        // Stage W (padded to 20 cols) while cp.asyncs fly
        for (int i = t; i < DIMD * ZS; i += THREADS) {
            int dd = i / ZS, c = i - dd * ZS;
            ws[i] = (c < NC) ? W[dd * NC + c] : 0.f;
        }

        ull acc[NPAIR];
        const ull z2 = pack2(0.f, 0.f);
#pragma unroll
        for (int j = 0; j < NPAIR; j++) acc[j] = z2;

        for (int s = 0; s < NSTAGE; s++) {
            cpwait2();            // stage s resident (<=2 younger pending)
            __syncthreads();      // writes visible; prior-buffer reads done
            if (s + 3 < NSTAGE) issue_stage(s + 3);
            cpcommit();

            const float4* xrow = (const float4*)&xs[s % DEPTH][t * XSTRIDE];
            const ulonglong2* wq = (const ulonglong2*)(ws + s * DCHUNK * ZS);
#pragma unroll
            for (int k = 0; k < 2; k++) {
                float4 xv = xrow[k];             // LDS.128, conflict-free
                float xf[4] = {xv.x, xv.y, xv.z, xv.w};
#pragma unroll
                for (int m = 0; m < 4; m++) {
                    int dd = k * 4 + m;
                    ull xaa = pack2(xf[m], xf[m]);
#pragma unroll
                    for (int jj = 0; jj < 5; jj++) {
                        ulonglong2 w = wq[dd * 5 + jj];  // LDS.128 broadcast
                        fma2(acc[2 * jj],     xaa, w.x);
                        fma2(acc[2 * jj + 1], xaa, w.y);
                    }
                }
            }
        }

        ulonglong2* za = (ulonglong2*)&g_Z[(size_t)(row0 + t) * ZS];
#pragma unroll
        for (int jj = 0; jj < 5; jj++) {
            ulonglong2 sa; sa.x = acc[2 * jj]; sa.y = acc[2 * jj + 1];
            za[jj] = sa;
        }
    } else {
        // ----------------- segment bounds part -----------------
        const int base = (blockIdx.x - PROJ_BLOCKS) * (THREADS * PPT)
                       + threadIdx.x * PPT;
        if (base >= P) return;
        int vv[PPT];
        const int4* s4 = (const int4*)(segs + base);
#pragma unroll
        for (int q = 0; q < PPT / 4; q++) {
            int4 v = __ldg(s4 + q);
            vv[q*4+0] = v.x; vv[q*4+1] = v.y; vv[q*4+2] = v.z; vv[q*4+3] = v.w;
        }
        int prev = (base == 0) ? -1 : __ldg(segs + base - 1);
#pragma unroll
        for (int k = 0; k < PPT; k++) {
            int s = vv[k];
            if (s != prev)
                for (int q = prev + 1; q <= s; q++) g_off[q] = base + k;
            prev = s;
        }
        if (base + PPT >= P)
            for (int q = prev + 1; q <= NISEG; q++) g_off[q] = P;
    }
}

// ---------------------------------------------------------------------------
// Seg kernel: one WARP per segment, no shared memory, no block syncs.
// 3 groups x 10 f32x2-pair lanes; 64-bit shfl reduction; mean+bias+sigmoid.
// ---------------------------------------------------------------------------
__global__ __launch_bounds__(32 * SEGS_PER_BLOCK)
void seg_kernel(const int* __restrict__ pidx, const float* __restrict__ bias,
                float* __restrict__ out) {
    const int lane = threadIdx.x & 31;
    const int s = blockIdx.x * SEGS_PER_BLOCK + (threadIdx.x >> 5);

    const int start = __ldg(&g_off[s]);
    const int end   = __ldg(&g_off[s + 1]);

    const int g = lane / NPAIR;      // 0..2 active, 3 = lanes 30,31 idle
    const int j = lane - g * NPAIR;  // column pair 0..9

    ull acc = 0;
    if (g < 3) {
#pragma unroll 4
        for (int p = start + g; p < end; p += 3) {
            int r = __ldg(pidx + p);                     // group-broadcast
            ull v = *(const ull*)&g_Z[(size_t)r * ZS + 2 * j];
            add2(acc, v);
        }
    }

    // reduce groups 0..2 down to lanes 0..9
    ull v1 = __shfl_down_sync(0xffffffffu, acc, 10);
    ull v2 = __shfl_down_sync(0xffffffffu, acc, 20);
    add2(acc, v1);
    add2(acc, v2);

    if (lane < NPAIR) {
        float f0, f1; unpack2(acc, f0, f1);
        float cnt = (float)(end - start);
        float inv = 1.0f / fmaxf(cnt, 1.0f);
        int c0 = 2 * lane;
        float x0 = f0 * inv + __ldg(bias + c0);
        out[(size_t)s * NC + c0] = 1.0f / (1.0f + __expf(-x0));
        if (c0 + 1 < NC) {
            float x1 = f1 * inv + __ldg(bias + c0 + 1);
            out[(size_t)s * NC + c0 + 1] = 1.0f / (1.0f + __expf(-x1));
        }
    }
}

// ---------------------------------------------------------------------------
extern "C" void kernel_launch(void* const* d_in, const int* in_sizes, int n_in,
                              void* d_out, int out_size) {
    const float* X    = (const float*)d_in[0];
    const float* W    = (const float*)d_in[1];
    const float* b    = (const float*)d_in[2];
    const int*   pidx = (const int*)d_in[3];
    const int*   segs = (const int*)d_in[4];
    float*       out  = (float*)d_out;

    const int P = in_sizes[3];
    const int boundsBlocks = (P + THREADS * PPT - 1) / (THREADS * PPT);

    fat_kernel<<<PROJ_BLOCKS + boundsBlocks, THREADS>>>(X, W, segs, P);
    seg_kernel<<<NISEG / SEGS_PER_BLOCK, 32 * SEGS_PER_BLOCK>>>(pidx, b, out);
}

// round 7
// speedup vs baseline: 1.1844x; 1.0754x over previous
#include <cuda_runtime.h>

// Fixed problem shapes
#define DIMD 272
#define NC   19
#define ZS   20
#define NPAIR 10
#define NROWS 65536
#define NISEG 4096
#define THREADS 128
#define PB_ROWS 128                      // rows per proj block (1/thread)
#define PROJ_BLOCKS (NROWS / PB_ROWS)    // 512
#define DCHUNK 8                         // d's per stage (272 = 34*8)
#define NSTAGE 34
#define DEPTH 4                          // per-lane cp.async ring depth
#define LSTRIDE 48                       // bytes per lane per stage buffer
#define STAGE_BYTES (PB_ROWS * LSTRIDE)  // 6144
#define PPT 16                           // points/thread in bounds part

typedef unsigned long long ull;

__device__ float g_Z[(size_t)NROWS * ZS];
__device__ int   g_off[NISEG + 1];

__device__ __forceinline__ ull pack2(float lo, float hi) {
    ull r; asm("mov.b64 %0, {%1, %2};" : "=l"(r) : "f"(lo), "f"(hi)); return r;
}
__device__ __forceinline__ void unpack2(ull v, float& lo, float& hi) {
    asm("mov.b64 {%0, %1}, %2;" : "=f"(lo), "=f"(hi) : "l"(v));
}
__device__ __forceinline__ void fma2(ull& d, ull a, ull b) {
    asm("fma.rn.f32x2 %0, %1, %2, %0;" : "+l"(d) : "l"(a), "l"(b));
}
__device__ __forceinline__ void add2(ull& d, ull a) {
    asm("add.rn.f32x2 %0, %0, %1;" : "+l"(d) : "l"(a));
}
__device__ __forceinline__ void cpasync16(unsigned smem, const void* g) {
    asm volatile("cp.async.cg.shared.global [%0], [%1], 16;"
                 :: "r"(smem), "l"(g));
}
__device__ __forceinline__ void cpcommit() {
    asm volatile("cp.async.commit_group;");
}
__device__ __forceinline__ void cpwait3() {
    asm volatile("cp.async.wait_group 3;");
}

// ---------------------------------------------------------------------------
// Fat kernel: blocks [0, PROJ_BLOCKS) compute Z = X@W with a SYNC-FREE
// per-lane cp.async pipeline (producer == consumer, so no barriers needed);
// remaining blocks compute segment boundary offsets.
// ---------------------------------------------------------------------------
__global__ __launch_bounds__(THREADS)
void fat_kernel(const float* __restrict__ X, const float* __restrict__ W,
                const int* __restrict__ segs, int P) {
    if (blockIdx.x < PROJ_BLOCKS) {
        __shared__ __align__(16) float ws[DIMD * ZS];          // 21760 B
        __shared__ __align__(16) char  xs[DEPTH * STAGE_BYTES]; // 24576 B

        const int t = threadIdx.x;
        const int row = blockIdx.x * PB_ROWS + t;
        const char* grow = (const char*)(X + (size_t)row * DIMD);
        const unsigned lbase =
            (unsigned)__cvta_generic_to_shared(xs) + (unsigned)(t * LSTRIDE);

        // Per-thread stage issue: copy THIS thread's 32-B row chunk.
        auto issue_stage = [&](int s) {
            unsigned dst = lbase + (unsigned)((s & (DEPTH - 1)) * STAGE_BYTES);
            const char* src = grow + (size_t)s * 32;
            cpasync16(dst, src);
            cpasync16(dst + 16, src + 16);
        };

        issue_stage(0); cpcommit();
        issue_stage(1); cpcommit();
        issue_stage(2); cpcommit();

        // Stage W (padded to 20 cols) while cp.asyncs fly
        for (int i = t; i < DIMD * ZS; i += THREADS) {
            int dd = i / ZS, c = i - dd * ZS;
            ws[i] = (c < NC) ? W[dd * NC + c] : 0.f;
        }
        __syncthreads();      // only barrier: ws visible to all

        ull acc[NPAIR];
        const ull z2 = pack2(0.f, 0.f);
#pragma unroll
        for (int j = 0; j < NPAIR; j++) acc[j] = z2;

        for (int s = 0; s < NSTAGE; s++) {
            if (s + 3 < NSTAGE) issue_stage(s + 3);
            cpcommit();
            cpwait3();        // this thread's stage-s chunk resident

            const float4* xq = (const float4*)
                (xs + (s & (DEPTH - 1)) * STAGE_BYTES + t * LSTRIDE);
            const ulonglong2* wq = (const ulonglong2*)(ws + s * DCHUNK * ZS);
#pragma unroll
            for (int k = 0; k < 2; k++) {
                float4 xv = xq[k];
                float xf[4] = {xv.x, xv.y, xv.z, xv.w};
#pragma unroll
                for (int m = 0; m < 4; m++) {
                    int dd = k * 4 + m;
                    ull xaa = pack2(xf[m], xf[m]);
#pragma unroll
                    for (int jj = 0; jj < 5; jj++) {
                        ulonglong2 w = wq[dd * 5 + jj];  // LDS.128 broadcast
                        fma2(acc[2 * jj],     xaa, w.x);
                        fma2(acc[2 * jj + 1], xaa, w.y);
                    }
                }
            }
        }

        ulonglong2* za = (ulonglong2*)&g_Z[(size_t)row * ZS];
#pragma unroll
        for (int jj = 0; jj < 5; jj++) {
            ulonglong2 sa; sa.x = acc[2 * jj]; sa.y = acc[2 * jj + 1];
            za[jj] = sa;
        }
    } else {
        // ----------------- segment bounds part -----------------
        const int base = (blockIdx.x - PROJ_BLOCKS) * (THREADS * PPT)
                       + threadIdx.x * PPT;
        if (base >= P) return;
        int vv[PPT];
        const int4* s4 = (const int4*)(segs + base);
#pragma unroll
        for (int q = 0; q < PPT / 4; q++) {
            int4 v = __ldg(s4 + q);
            vv[q*4+0] = v.x; vv[q*4+1] = v.y; vv[q*4+2] = v.z; vv[q*4+3] = v.w;
        }
        int prev = (base == 0) ? -1 : __ldg(segs + base - 1);
#pragma unroll
        for (int k = 0; k < PPT; k++) {
            int s = vv[k];
            if (s != prev)
                for (int q = prev + 1; q <= s; q++) g_off[q] = base + k;
            prev = s;
        }
        if (base + PPT >= P)
            for (int q = prev + 1; q <= NISEG; q++) g_off[q] = P;
    }
}

// ---------------------------------------------------------------------------
// Seg kernel: 2 warps per segment (stride-6 interleave), explicit MLP-4
// batched loads, shfl + one shared combine; mean + bias + sigmoid.
// Block = 256 threads = 8 warps = 4 segments.
// ---------------------------------------------------------------------------
__global__ __launch_bounds__(256)
void seg_kernel(const int* __restrict__ pidx, const float* __restrict__ bias,
                float* __restrict__ out) {
    const int t = threadIdx.x;
    const int w = t >> 5;
    const int lane = t & 31;
    const int h = w & 1;                        // half of segment
    const int s = blockIdx.x * 4 + (w >> 1);

    const int start = __ldg(&g_off[s]);
    const int end   = __ldg(&g_off[s + 1]);

    const int g = lane / NPAIR;                 // 0..2 active; lanes 30,31 idle
    const int j = lane - g * NPAIR;

    __shared__ ull sAcc[8 * NPAIR];

    ull acc0 = 0, acc1 = 0;
    if (g < 3) {
        int p = start + 3 * h + g;              // stride 6 across both warps
        // MLP-4 batches
        for (; p + 18 < end; p += 24) {
            int r0 = __ldg(pidx + p);
            int r1 = __ldg(pidx + p + 6);
            int r2 = __ldg(pidx + p + 12);
            int r3 = __ldg(pidx + p + 18);
            ull v0 = *(const ull*)&g_Z[(size_t)r0 * ZS + 2 * j];
            ull v1 = *(const ull*)&g_Z[(size_t)r1 * ZS + 2 * j];
            ull v2 = *(const ull*)&g_Z[(size_t)r2 * ZS + 2 * j];
            ull v3 = *(const ull*)&g_Z[(size_t)r3 * ZS + 2 * j];
            add2(acc0, v0); add2(acc1, v1);
            add2(acc0, v2); add2(acc1, v3);
        }
        for (; p < end; p += 6) {
            int r = __ldg(pidx + p);
            ull v = *(const ull*)&g_Z[(size_t)r * ZS + 2 * j];
            add2(acc0, v);
        }
        add2(acc0, acc1);
    }

    // reduce 3 groups -> lanes 0..9
    ull v1 = __shfl_down_sync(0xffffffffu, acc0, 10);
    ull v2 = __shfl_down_sync(0xffffffffu, acc0, 20);
    add2(acc0, v1);
    add2(acc0, v2);

    if (lane < NPAIR) sAcc[w * NPAIR + lane] = acc0;
    __syncthreads();

    if (h == 0 && lane < NPAIR) {
        ull total = sAcc[w * NPAIR + lane];
        add2(total, sAcc[(w + 1) * NPAIR + lane]);
        float f0, f1; unpack2(total, f0, f1);
        float cnt = (float)(end - start);
        float inv = 1.0f / fmaxf(cnt, 1.0f);
        int c0 = 2 * lane;
        float x0 = f0 * inv + __ldg(bias + c0);
        out[(size_t)s * NC + c0] = 1.0f / (1.0f + __expf(-x0));
        if (c0 + 1 < NC) {
            float x1 = f1 * inv + __ldg(bias + c0 + 1);
            out[(size_t)s * NC + c0 + 1] = 1.0f / (1.0f + __expf(-x1));
        }
    }
}

// ---------------------------------------------------------------------------
extern "C" void kernel_launch(void* const* d_in, const int* in_sizes, int n_in,
                              void* d_out, int out_size) {
    const float* X    = (const float*)d_in[0];
    const float* W    = (const float*)d_in[1];
    const float* b    = (const float*)d_in[2];
    const int*   pidx = (const int*)d_in[3];
    const int*   segs = (const int*)d_in[4];
    float*       out  = (float*)d_out;

    const int P = in_sizes[3];
    const int boundsBlocks = (P + THREADS * PPT - 1) / (THREADS * PPT);

    fat_kernel<<<PROJ_BLOCKS + boundsBlocks, THREADS>>>(X, W, segs, P);
    seg_kernel<<<NISEG / 4, 256>>>(pidx, b, out);
}

// round 8
// speedup vs baseline: 1.3777x; 1.1633x over previous
#include <cuda_runtime.h>

// Fixed problem shapes
#define DIMD 272
#define NC   19
#define WCOLS 20                 // padded W cols (10 f32x2 pairs)
#define NPAIR 10
#define ZROWF 32                 // Z row stride in floats = 128 B (1 line)
#define NROWS 65536
#define NISEG 4096
#define THREADS 128
#define PB_ROWS 256              // rows per proj block (2 per thread)
#define PROJ_BLOCKS (NROWS / PB_ROWS)   // 256
#define SDW 16                   // d's per stage (272 = 17*16)
#define NSTAGE 17
#define XST 80                   // stage row stride bytes (64 data + 16 pad)
#define STAGE_BYTES (PB_ROWS * XST)     // 20480
#define DEPTH 3
#define WS_BYTES (DIMD * WCOLS * 4)     // 21760
#define SMEM_DYN (DEPTH * STAGE_BYTES + WS_BYTES)  // 83200
#define PPT 16                   // points/thread in bounds part

typedef unsigned long long ull;

__device__ float g_Z[(size_t)NROWS * ZROWF];    // 8 MB, 128B rows
__device__ int   g_off[NISEG + 1];

__device__ __forceinline__ ull pack2(float lo, float hi) {
    ull r; asm("mov.b64 %0, {%1, %2};" : "=l"(r) : "f"(lo), "f"(hi)); return r;
}
__device__ __forceinline__ void unpack2(ull v, float& lo, float& hi) {
    asm("mov.b64 {%0, %1}, %2;" : "=f"(lo), "=f"(hi) : "l"(v));
}
__device__ __forceinline__ void fma2(ull& d, ull a, ull b) {
    asm("fma.rn.f32x2 %0, %1, %2, %0;" : "+l"(d) : "l"(a), "l"(b));
}
__device__ __forceinline__ void add2(ull& d, ull a) {
    asm("add.rn.f32x2 %0, %0, %1;" : "+l"(d) : "l"(a));
}
__device__ __forceinline__ void cpasync16(unsigned smem, const void* g) {
    asm volatile("cp.async.cg.shared.global [%0], [%1], 16;"
                 :: "r"(smem), "l"(g));
}
__device__ __forceinline__ void cpcommit() {
    asm volatile("cp.async.commit_group;");
}
__device__ __forceinline__ void cpwait1() {
    asm volatile("cp.async.wait_group 1;");
}

// ---------------------------------------------------------------------------
// Fat kernel: blocks [0, PROJ_BLOCKS) compute Z = X@W with warp-COALESCED
// cp.async staging (nL=8 lines/instr) + 2 rows/thread; remaining blocks
// compute segment boundary offsets.
// ---------------------------------------------------------------------------
__global__ __launch_bounds__(THREADS)
void fat_kernel(const float* __restrict__ X, const float* __restrict__ W,
                const int* __restrict__ segs, int P) {
    extern __shared__ __align__(16) char smem[];
    float* ws = (float*)smem;                 // 21760 B
    char*  xs = smem + WS_BYTES;              // DEPTH stage buffers

    if (blockIdx.x < PROJ_BLOCKS) {
        const int t = threadIdx.x;
        const int row0 = blockIdx.x * PB_ROWS;
        const char* gX = (const char*)(X + (size_t)row0 * DIMD);

        // Coalesced stage issue: 256 rows x 64 B; threads 0..3 cover one row
        // (64 B = one aligned half/whole-line span since 1088 = 17*64).
        auto issue_stage = [&](int s) {
            unsigned sb = (unsigned)__cvta_generic_to_shared(xs)
                        + (unsigned)((s % DEPTH) * STAGE_BYTES);
            const char* gbase = gX + (size_t)s * 64;
#pragma unroll
            for (int k = 0; k < 8; k++) {
                int i = t + k * THREADS;          // 0..1023
                int r = i >> 2;
                int c = i & 3;
                cpasync16(sb + (unsigned)(r * XST + c * 16),
                          gbase + (size_t)r * (DIMD * 4) + c * 16);
            }
        };

        issue_stage(0); cpcommit();
        issue_stage(1); cpcommit();

        // Stage W (padded to 20 cols) while cp.asyncs fly
        for (int i = t; i < DIMD * WCOLS; i += THREADS) {
            int dd = i / WCOLS, c = i - dd * WCOLS;
            ws[i] = (c < NC) ? W[dd * NC + c] : 0.f;
        }
        __syncthreads();

        ull accA[NPAIR], accB[NPAIR];
        const ull z2 = pack2(0.f, 0.f);
#pragma unroll
        for (int j = 0; j < NPAIR; j++) { accA[j] = z2; accB[j] = z2; }

        for (int s = 0; s < NSTAGE; s++) {
            cpwait1();            // all but newest group done -> stage s ready
            __syncthreads();      // everyone past compute(s-1), stage s visible
            if (s + 2 < NSTAGE) issue_stage(s + 2);
            cpcommit();           // unconditional: keeps group count uniform

            const char* sbase = xs + (s % DEPTH) * STAGE_BYTES;
            const float4* xa = (const float4*)(sbase + t * XST);
            const float4* xb = (const float4*)(sbase + (t + 128) * XST);
            const ulonglong2* wq = (const ulonglong2*)(ws + s * SDW * WCOLS);
#pragma unroll
            for (int k = 0; k < 4; k++) {
                float4 va = xa[k];                 // LDS.128, conflict-free
                float4 vb = xb[k];
                float fa[4] = {va.x, va.y, va.z, va.w};
                float fb[4] = {vb.x, vb.y, vb.z, vb.w};
#pragma unroll
                for (int m = 0; m < 4; m++) {
                    int dd = k * 4 + m;
                    ull xaa = pack2(fa[m], fa[m]);
                    ull xbb = pack2(fb[m], fb[m]);
#pragma unroll
                    for (int jj = 0; jj < 5; jj++) {
                        ulonglong2 w = wq[dd * 5 + jj];   // LDS.128 broadcast
                        fma2(accA[2 * jj],     xaa, w.x);
                        fma2(accA[2 * jj + 1], xaa, w.y);
                        fma2(accB[2 * jj],     xbb, w.x);
                        fma2(accB[2 * jj + 1], xbb, w.y);
                    }
                }
            }
        }

        ulonglong2* za = (ulonglong2*)&g_Z[(size_t)(row0 + t) * ZROWF];
        ulonglong2* zb = (ulonglong2*)&g_Z[(size_t)(row0 + t + 128) * ZROWF];
#pragma unroll
        for (int jj = 0; jj < 5; jj++) {
            ulonglong2 sa; sa.x = accA[2 * jj]; sa.y = accA[2 * jj + 1];
            ulonglong2 sb; sb.x = accB[2 * jj]; sb.y = accB[2 * jj + 1];
            za[jj] = sa; zb[jj] = sb;
        }
    } else {
        // ----------------- segment bounds part -----------------
        const int base = (blockIdx.x - PROJ_BLOCKS) * (THREADS * PPT)
                       + threadIdx.x * PPT;
        if (base >= P) return;
        int vv[PPT];
        const int4* s4 = (const int4*)(segs + base);
#pragma unroll
        for (int q = 0; q < PPT / 4; q++) {
            int4 v = __ldg(s4 + q);
            vv[q*4+0] = v.x; vv[q*4+1] = v.y; vv[q*4+2] = v.z; vv[q*4+3] = v.w;
        }
        int prev = (base == 0) ? -1 : __ldg(segs + base - 1);
#pragma unroll
        for (int k = 0; k < PPT; k++) {
            int s = vv[k];
            if (s != prev)
                for (int q = prev + 1; q <= s; q++) g_off[q] = base + k;
            prev = s;
        }
        if (base + PPT >= P)
            for (int q = prev + 1; q <= NISEG; q++) g_off[q] = P;
    }
}

// ---------------------------------------------------------------------------
// Seg kernel: 2 warps/segment, 3 groups x 10 pair-lanes, MLP-4 batches.
// Z rows are 128-B aligned -> one L1tex wavefront per row gather.
// ---------------------------------------------------------------------------
__global__ __launch_bounds__(256)
void seg_kernel(const int* __restrict__ pidx, const float* __restrict__ bias,
                float* __restrict__ out) {
    const int t = threadIdx.x;
    const int w = t >> 5;
    const int lane = t & 31;
    const int h = w & 1;
    const int s = blockIdx.x * 4 + (w >> 1);

    const int start = __ldg(&g_off[s]);
    const int end   = __ldg(&g_off[s + 1]);

    const int g = lane / NPAIR;          // 0..2 active; lanes 30,31 idle
    const int j = lane - g * NPAIR;

    __shared__ ull sAcc[8 * NPAIR];

    ull acc0 = 0, acc1 = 0;
    if (g < 3) {
        int p = start + 3 * h + g;       // stride 6 across both warps
        for (; p + 18 < end; p += 24) {
            int r0 = __ldg(pidx + p);
            int r1 = __ldg(pidx + p + 6);
            int r2 = __ldg(pidx + p + 12);
            int r3 = __ldg(pidx + p + 18);
            ull v0 = *(const ull*)&g_Z[(size_t)r0 * ZROWF + 2 * j];
            ull v1 = *(const ull*)&g_Z[(size_t)r1 * ZROWF + 2 * j];
            ull v2 = *(const ull*)&g_Z[(size_t)r2 * ZROWF + 2 * j];
            ull v3 = *(const ull*)&g_Z[(size_t)r3 * ZROWF + 2 * j];
            add2(acc0, v0); add2(acc1, v1);
            add2(acc0, v2); add2(acc1, v3);
        }
        for (; p < end; p += 6) {
            int r = __ldg(pidx + p);
            ull v = *(const ull*)&g_Z[(size_t)r * ZROWF + 2 * j];
            add2(acc0, v);
        }
        add2(acc0, acc1);
    }

    ull v1 = __shfl_down_sync(0xffffffffu, acc0, 10);
    ull v2 = __shfl_down_sync(0xffffffffu, acc0, 20);
    add2(acc0, v1);
    add2(acc0, v2);

    if (lane < NPAIR) sAcc[w * NPAIR + lane] = acc0;
    __syncthreads();

    if (h == 0 && lane < NPAIR) {
        ull total = sAcc[w * NPAIR + lane];
        add2(total, sAcc[(w + 1) * NPAIR + lane]);
        float f0, f1; unpack2(total, f0, f1);
        float cnt = (float)(end - start);
        float inv = 1.0f / fmaxf(cnt, 1.0f);
        int c0 = 2 * lane;
        float x0 = f0 * inv + __ldg(bias + c0);
        out[(size_t)s * NC + c0] = 1.0f / (1.0f + __expf(-x0));
        if (c0 + 1 < NC) {
            float x1 = f1 * inv + __ldg(bias + c0 + 1);
            out[(size_t)s * NC + c0 + 1] = 1.0f / (1.0f + __expf(-x1));
        }
    }
}

// ---------------------------------------------------------------------------
extern "C" void kernel_launch(void* const* d_in, const int* in_sizes, int n_in,
                              void* d_out, int out_size) {
    const float* X    = (const float*)d_in[0];
    const float* W    = (const float*)d_in[1];
    const float* b    = (const float*)d_in[2];
    const int*   pidx = (const int*)d_in[3];
    const int*   segs = (const int*)d_in[4];
    float*       out  = (float*)d_out;

    const int P = in_sizes[3];
    const int boundsBlocks = (P + THREADS * PPT - 1) / (THREADS * PPT);

    static int attr_done = 0;
    if (!attr_done) {
        cudaFuncSetAttribute(fat_kernel,
                             cudaFuncAttributeMaxDynamicSharedMemorySize,
                             SMEM_DYN);
        attr_done = 1;
    }

    fat_kernel<<<PROJ_BLOCKS + boundsBlocks, THREADS, SMEM_DYN>>>(X, W, segs, P);
    seg_kernel<<<NISEG / 4, 256>>>(pidx, b, out);
}